// round 14
// baseline (speedup 1.0000x reference)
#include <cuda_runtime.h>
#include <cuda_bf16.h>
#include <mma.h>
#include <stdint.h>
#include <string.h>
#include <math.h>

using namespace nvcuda;

// Problem constants (shapes fixed by the dataset)
#define NMAX   100000
#define EMAX   1600000
#define TOTMAX (NMAX + EMAX)
#define HC     128   // HEADS*OUT_C
#define HEADS  8
#define NEG_SLOPE 0.2f
#define SCAN_B 256
#define MAXBLK ((NMAX + SCAN_B - 1) / SCAN_B)   // 391
#define LD     136   // smem leading dim (elements); 272B rows for bf16

// -------- scratch (static __device__ globals: allocation-guard-safe) --------
__device__ float g_xw[(size_t)NMAX * HC];     // projected features [N,128]
__device__ float g_as[(size_t)NMAX * HEADS];  // per-node src attention term
__device__ float g_ad[(size_t)NMAX * HEADS];  // per-node dst attention term
__device__ int   g_cnt[NMAX];                 // per-dst real-edge degree
__device__ int   g_off[NMAX + 1];             // CSR offsets (incl. self loop)
__device__ int   g_cursor[NMAX];              // scatter cursors
__device__ int   g_srt_src[TOTMAX];           // src node ids, grouped by dst
__device__ int   g_tpre[MAXBLK * SCAN_B];     // per-thread inclusive prefixes
__device__ int   g_bsum[MAXBLK];              // per-block totals
__device__ int   g_boff[MAXBLK];              // exclusive block offsets

__device__ __forceinline__ uint32_t bf2_as_u32(__nv_bfloat162 v) {
    uint32_t u;
    memcpy(&u, &v, 4);
    return u;
}

// ---------------------------------------------------------------------------
// K1: tensor-core GEMM via wmma (HMMA, sm_80+ PTX — no 'a'-target features).
// Per CTA: 128 rows of x, full 128x128 W, K=128, bf16x3 split, f32 accum.
// smem: sAh | sAl | sBh | sBl (bf16, ld=136). Epilogue stages f32 result
// into the A region, then writes g_xw + a_s/a_d dots coalesced.
// ---------------------------------------------------------------------------
__global__ __launch_bounds__(256) void k_gemm_wmma(
    const float* __restrict__ x, const float* __restrict__ W,
    const float* __restrict__ att_src, const float* __restrict__ att_dst, int N)
{
    extern __shared__ char smem[];
    __nv_bfloat16* sAh = (__nv_bfloat16*)smem;                    // 128*136 bf16
    __nv_bfloat16* sAl = sAh + 128 * LD;
    __nv_bfloat16* sBh = sAl + 128 * LD;
    __nv_bfloat16* sBl = sBh + 128 * LD;

    int tid = threadIdx.x, wid = tid >> 5, lane = tid & 31;
    int tile0 = blockIdx.x * 128;

    // ---- convert A (x rows) to bf16 hi/lo ----
    for (int r = wid; r < 128; r += 8) {
        int grow = tile0 + r;
        float4 v = make_float4(0.f, 0.f, 0.f, 0.f);
        if (grow < N)
            v = *reinterpret_cast<const float4*>(x + (size_t)grow * HC + lane * 4);
        __nv_bfloat162 h01 = __floats2bfloat162_rn(v.x, v.y);
        __nv_bfloat162 h23 = __floats2bfloat162_rn(v.z, v.w);
        float2 f01 = __bfloat1622float2(h01);
        float2 f23 = __bfloat1622float2(h23);
        __nv_bfloat162 l01 = __floats2bfloat162_rn(v.x - f01.x, v.y - f01.y);
        __nv_bfloat162 l23 = __floats2bfloat162_rn(v.z - f23.x, v.w - f23.y);
        *reinterpret_cast<uint2*>(sAh + r * LD + lane * 4) =
            make_uint2(bf2_as_u32(h01), bf2_as_u32(h23));
        *reinterpret_cast<uint2*>(sAl + r * LD + lane * 4) =
            make_uint2(bf2_as_u32(l01), bf2_as_u32(l23));
    }
    // ---- convert B (W rows, [k][n] row-major as-is) ----
    for (int k = wid; k < 128; k += 8) {
        float4 v = __ldg(reinterpret_cast<const float4*>(W + k * HC + lane * 4));
        __nv_bfloat162 h01 = __floats2bfloat162_rn(v.x, v.y);
        __nv_bfloat162 h23 = __floats2bfloat162_rn(v.z, v.w);
        float2 f01 = __bfloat1622float2(h01);
        float2 f23 = __bfloat1622float2(h23);
        __nv_bfloat162 l01 = __floats2bfloat162_rn(v.x - f01.x, v.y - f01.y);
        __nv_bfloat162 l23 = __floats2bfloat162_rn(v.z - f23.x, v.w - f23.y);
        *reinterpret_cast<uint2*>(sBh + k * LD + lane * 4) =
            make_uint2(bf2_as_u32(h01), bf2_as_u32(h23));
        *reinterpret_cast<uint2*>(sBl + k * LD + lane * 4) =
            make_uint2(bf2_as_u32(l01), bf2_as_u32(l23));
    }
    __syncthreads();

    // ---- GEMM: warp owns rows [wid*16, wid*16+16), all 128 cols ----
    wmma::fragment<wmma::accumulator, 16, 16, 16, float> acc[8];
#pragma unroll
    for (int j = 0; j < 8; j++) wmma::fill_fragment(acc[j], 0.f);

    int row0 = wid * 16;
#pragma unroll
    for (int kk = 0; kk < 128; kk += 16) {
        wmma::fragment<wmma::matrix_a, 16, 16, 16, __nv_bfloat16, wmma::row_major> ah, al;
        wmma::load_matrix_sync(ah, sAh + row0 * LD + kk, LD);
        wmma::load_matrix_sync(al, sAl + row0 * LD + kk, LD);
#pragma unroll
        for (int j = 0; j < 8; j++) {
            wmma::fragment<wmma::matrix_b, 16, 16, 16, __nv_bfloat16, wmma::row_major> bh, bl;
            wmma::load_matrix_sync(bh, sBh + kk * LD + j * 16, LD);
            wmma::load_matrix_sync(bl, sBl + kk * LD + j * 16, LD);
            wmma::mma_sync(acc[j], ah, bh, acc[j]);
            wmma::mma_sync(acc[j], ah, bl, acc[j]);
            wmma::mma_sync(acc[j], al, bh, acc[j]);
        }
    }
    __syncthreads();   // all warps done reading A/B before aliasing A region

    // ---- stage f32 result into smem (aliases sAh+sAl: 128*136*4 bytes) ----
    float* sOut = (float*)smem;
#pragma unroll
    for (int j = 0; j < 8; j++)
        wmma::store_matrix_sync(sOut + row0 * LD + j * 16, acc[j], LD,
                                wmma::mem_row_major);
    __syncthreads();

    // ---- epilogue: write g_xw + attention dots ----
    int h4 = lane >> 2;
    float4 asv = __ldg(reinterpret_cast<const float4*>(att_src + h4 * 16 + (lane & 3) * 4));
    float4 adv = __ldg(reinterpret_cast<const float4*>(att_dst + h4 * 16 + (lane & 3) * 4));

    for (int r = wid; r < 128; r += 8) {
        int grow = tile0 + r;
        if (grow >= N) continue;   // warp-uniform
        float4 v = *reinterpret_cast<const float4*>(sOut + r * LD + lane * 4);
        *reinterpret_cast<float4*>(g_xw + (size_t)grow * HC + lane * 4) = v;

        float sd = v.x * asv.x + v.y * asv.y + v.z * asv.z + v.w * asv.w;
        float dd = v.x * adv.x + v.y * adv.y + v.z * adv.z + v.w * adv.w;
        sd += __shfl_xor_sync(0xffffffffu, sd, 1);
        sd += __shfl_xor_sync(0xffffffffu, sd, 2);
        dd += __shfl_xor_sync(0xffffffffu, dd, 1);
        dd += __shfl_xor_sync(0xffffffffu, dd, 2);
        if ((lane & 3) == 0) {
            g_as[(size_t)grow * HEADS + h4] = sd;
            g_ad[(size_t)grow * HEADS + h4] = dd;
        }
    }
}

// ---------------------------------------------------------------------------
// K0: zero the per-dst counters (self loop is added in the scan)
// ---------------------------------------------------------------------------
__global__ __launch_bounds__(256) void k_zero(int N)
{
    int i = blockIdx.x * blockDim.x + threadIdx.x;
    if (i < N) g_cnt[i] = 0;
}

// ---------------------------------------------------------------------------
// K2: histogram of destination nodes (real edges only)
// ---------------------------------------------------------------------------
__global__ __launch_bounds__(256) void k_hist(const int* __restrict__ ei, int E)
{
    int e4 = blockIdx.x * blockDim.x + threadIdx.x;
    int base = e4 * 4;
    if (base + 4 <= E) {
        int4 d = *reinterpret_cast<const int4*>(ei + E + base);
        atomicAdd(&g_cnt[d.x], 1);
        atomicAdd(&g_cnt[d.y], 1);
        atomicAdd(&g_cnt[d.z], 1);
        atomicAdd(&g_cnt[d.w], 1);
    } else {
        for (int e = base; e < E; e++) atomicAdd(&g_cnt[ei[E + e]], 1);
    }
}

// ---------------------------------------------------------------------------
// K3a/b/c: grid-wide exclusive scan of (g_cnt[i] + 1)
// ---------------------------------------------------------------------------
__global__ __launch_bounds__(SCAN_B) void k_scanA(int N)
{
    __shared__ int sh[SCAN_B];
    int t = threadIdx.x;
    int i = blockIdx.x * SCAN_B + t;
    int v = (i < N) ? (g_cnt[i] + 1) : 0;
    sh[t] = v;
    __syncthreads();
#pragma unroll
    for (int off = 1; off < SCAN_B; off <<= 1) {
        int u = (t >= off) ? sh[t - off] : 0;
        __syncthreads();
        sh[t] += u;
        __syncthreads();
    }
    g_tpre[i] = sh[t];
    if (t == SCAN_B - 1) g_bsum[blockIdx.x] = sh[t];
}

__global__ __launch_bounds__(512) void k_scanB(int nb)
{
    __shared__ int sh[512];
    int t = threadIdx.x;
    int v = (t < nb) ? g_bsum[t] : 0;
    sh[t] = v;
    __syncthreads();
#pragma unroll
    for (int off = 1; off < 512; off <<= 1) {
        int u = (t >= off) ? sh[t - off] : 0;
        __syncthreads();
        sh[t] += u;
        __syncthreads();
    }
    if (t < nb) g_boff[t] = sh[t] - v;   // exclusive
}

__global__ __launch_bounds__(SCAN_B) void k_scanC(int N)
{
    int t = threadIdx.x;
    int i = blockIdx.x * SCAN_B + t;
    if (i >= N) return;
    int v    = g_cnt[i] + 1;
    int incl = g_boff[blockIdx.x] + g_tpre[i];
    int excl = incl - v;
    g_off[i]    = excl;
    g_cursor[i] = excl + 1;     // slot 0 of segment reserved for self loop
    g_srt_src[excl] = i;        // self loop src = node itself
    if (i == N - 1) g_off[N] = incl;
}

// ---------------------------------------------------------------------------
// K4: scatter real edges into dst-grouped order (x4 vectorized)
// ---------------------------------------------------------------------------
__global__ __launch_bounds__(256) void k_scatter(const int* __restrict__ ei, int E)
{
    int i = blockIdx.x * blockDim.x + threadIdx.x;
    int base = i * 4;
    if (base + 4 <= E) {
        int4 s = *reinterpret_cast<const int4*>(ei + base);
        int4 d = *reinterpret_cast<const int4*>(ei + E + base);
        g_srt_src[atomicAdd(&g_cursor[d.x], 1)] = s.x;
        g_srt_src[atomicAdd(&g_cursor[d.y], 1)] = s.y;
        g_srt_src[atomicAdd(&g_cursor[d.z], 1)] = s.z;
        g_srt_src[atomicAdd(&g_cursor[d.w], 1)] = s.w;
    } else {
        for (int e = base; e < E; e++) {
            int s = ei[e];
            int d = ei[E + e];
            g_srt_src[atomicAdd(&g_cursor[d], 1)] = s;
        }
    }
}

// ---------------------------------------------------------------------------
// K5: fused per-node softmax + aggregate + bias + relu. One warp per dst node.
// No max-subtraction (softmax shift-invariance; |logits| <= ~5 here).
// ---------------------------------------------------------------------------
__global__ __launch_bounds__(256) void k_agg(const float* __restrict__ bias,
                                             float* __restrict__ out, int N)
{
    int node = (blockIdx.x * blockDim.x + threadIdx.x) >> 5;
    int lane = threadIdx.x & 31;
    if (node >= N) return;

    int beg = g_off[node];
    int end = g_off[node + 1];

    int h = lane & 7;    // head whose logit this lane computes
    float ad = __ldg(&g_ad[(size_t)node * HEADS + h]);

    float denom = 0.f;
    float4 acc = make_float4(0.f, 0.f, 0.f, 0.f);

    int j = beg;
    for (; j + 2 <= end; j += 2) {
        int s0 = __ldg(&g_srt_src[j]);
        int s1 = __ldg(&g_srt_src[j + 1]);
        float e0 = __ldg(&g_as[(size_t)s0 * HEADS + h]) + ad;
        float e1 = __ldg(&g_as[(size_t)s1 * HEADS + h]) + ad;
        float4 v0 = __ldg(reinterpret_cast<const float4*>(g_xw + (size_t)s0 * HC + lane * 4));
        float4 v1 = __ldg(reinterpret_cast<const float4*>(g_xw + (size_t)s1 * HC + lane * 4));
        e0 = e0 > 0.f ? e0 : NEG_SLOPE * e0;
        e1 = e1 > 0.f ? e1 : NEG_SLOPE * e1;
        float p0 = __expf(e0);
        float p1 = __expf(e1);
        float a0 = __shfl_sync(0xffffffffu, p0, lane >> 2);  // alpha for head lane>>2
        float a1 = __shfl_sync(0xffffffffu, p1, lane >> 2);
        denom += a0 + a1;
        acc.x = fmaf(a0, v0.x, acc.x); acc.y = fmaf(a0, v0.y, acc.y);
        acc.z = fmaf(a0, v0.z, acc.z); acc.w = fmaf(a0, v0.w, acc.w);
        acc.x = fmaf(a1, v1.x, acc.x); acc.y = fmaf(a1, v1.y, acc.y);
        acc.z = fmaf(a1, v1.z, acc.z); acc.w = fmaf(a1, v1.w, acc.w);
    }
    if (j < end) {
        int s0 = __ldg(&g_srt_src[j]);
        float e0 = __ldg(&g_as[(size_t)s0 * HEADS + h]) + ad;
        float4 v0 = __ldg(reinterpret_cast<const float4*>(g_xw + (size_t)s0 * HC + lane * 4));
        e0 = e0 > 0.f ? e0 : NEG_SLOPE * e0;
        float p0 = __expf(e0);
        float a0 = __shfl_sync(0xffffffffu, p0, lane >> 2);
        denom += a0;
        acc.x = fmaf(a0, v0.x, acc.x); acc.y = fmaf(a0, v0.y, acc.y);
        acc.z = fmaf(a0, v0.z, acc.z); acc.w = fmaf(a0, v0.w, acc.w);
    }

    float inv = 1.f / (denom + 1e-16f);
    float4 b = *reinterpret_cast<const float4*>(bias + lane * 4);
    float4 o;
    o.x = fmaxf(fmaf(acc.x, inv, b.x), 0.f);
    o.y = fmaxf(fmaf(acc.y, inv, b.y), 0.f);
    o.z = fmaxf(fmaf(acc.z, inv, b.z), 0.f);
    o.w = fmaxf(fmaf(acc.w, inv, b.w), 0.f);
    *reinterpret_cast<float4*>(out + (size_t)node * HC + lane * 4) = o;
}

// ---------------------------------------------------------------------------
extern "C" void kernel_launch(void* const* d_in, const int* in_sizes, int n_in,
                              void* d_out, int out_size)
{
    const float* x       = (const float*)d_in[0];
    const int*   ei      = (const int*)  d_in[1];
    const float* W       = (const float*)d_in[2];
    const float* att_src = (const float*)d_in[3];
    const float* att_dst = (const float*)d_in[4];
    const float* bias    = (const float*)d_in[5];
    float* out = (float*)d_out;

    int N = in_sizes[0] / HC;
    int E = in_sizes[1] / 2;
    int nb = (N + SCAN_B - 1) / SCAN_B;

    const int GEMM_SMEM = 4 * 128 * LD * 2;   // 139264 B
    cudaFuncSetAttribute(k_gemm_wmma, cudaFuncAttributeMaxDynamicSharedMemorySize,
                         GEMM_SMEM);

    int gemm_blocks = (N + 127) / 128;
    k_gemm_wmma<<<gemm_blocks, 256, GEMM_SMEM>>>(x, W, att_src, att_dst, N);

    k_zero<<<(N + 255) / 256, 256>>>(N);
    int bh = ((E + 3) / 4 + 255) / 256;
    k_hist<<<bh, 256>>>(ei, E);

    k_scanA<<<nb, SCAN_B>>>(N);
    k_scanB<<<1, 512>>>(nb);
    k_scanC<<<nb, SCAN_B>>>(N);

    int bs = ((E + 3) / 4 + 255) / 256;
    k_scatter<<<bs, 256>>>(ei, E);

    long long aggthreads = (long long)N * 32;
    int ba = (int)((aggthreads + 255) / 256);
    k_agg<<<ba, 256>>>(bias, out, N);
}